// round 8
// baseline (speedup 1.0000x reference)
#include <cuda_runtime.h>

// Fused 2-layer LSTM, H=6, B=4096, T=1024.
// 8 threads per batch element; lane j = tid&7 owns hidden index j (j<6 active).
// Software-pipelined: each loop body computes layer0 step t AND layer1 step t-1,
// which are data-independent chains the warp scheduler can interleave
// (halves the exposed recurrent latency vs serial L0->L1).
// Weights register-resident, packed f32x2; dot products via fma.rn.f32x2.

#define T_STEPS 1024

__device__ __forceinline__ unsigned long long ffma2(unsigned long long a,
                                                    unsigned long long b,
                                                    unsigned long long c) {
    unsigned long long d;
    asm("fma.rn.f32x2 %0, %1, %2, %3;" : "=l"(d) : "l"(a), "l"(b), "l"(c));
    return d;
}

__device__ __forceinline__ unsigned long long pack2(float lo, float hi) {
    unsigned long long r;
    asm("mov.b64 %0, {%1, %2};" : "=l"(r) : "f"(lo), "f"(hi));
    return r;
}

__device__ __forceinline__ void unpack2(unsigned long long v, float& lo, float& hi) {
    asm("mov.b64 {%0, %1}, %2;" : "=f"(lo), "=f"(hi) : "l"(v));
}

__device__ __forceinline__ float sigmoid_f(float x) {
    return __fdividef(1.0f, 1.0f + __expf(-x));
}

__device__ __forceinline__ float tanh_f(float x) {
    return 1.0f - 2.0f * __fdividef(1.0f, 1.0f + __expf(2.0f * x));
}

// One LSTM cell step for the hidden index owned by this lane.
// in[3]: packed input vector (6 floats), hprev[3]: packed previous hidden,
// c: cell state (in/out). Returns h_j (this lane's new hidden component).
__device__ __forceinline__ float cell_step(
    const unsigned long long Wi[4][3], const unsigned long long Wh[4][3],
    const float B[4], const unsigned long long in[3],
    const unsigned long long hprev[3], float& c)
{
    float gv[4];
#pragma unroll
    for (int g = 0; g < 4; g++) {
        // x-part first (independent of recurrent state)
        unsigned long long acc = pack2(B[g], 0.0f);
        acc = ffma2(Wi[g][0], in[0], acc);
        acc = ffma2(Wi[g][1], in[1], acc);
        acc = ffma2(Wi[g][2], in[2], acc);
        // h-part (recurrent critical path: 3 ffma2)
        acc = ffma2(Wh[g][0], hprev[0], acc);
        acc = ffma2(Wh[g][1], hprev[1], acc);
        acc = ffma2(Wh[g][2], hprev[2], acc);
        float lo, hi;
        unpack2(acc, lo, hi);
        gv[g] = lo + hi;
    }
    const float ig = sigmoid_f(gv[0]);
    const float fg = sigmoid_f(gv[1]);
    const float gg = tanh_f(gv[2]);
    const float og = sigmoid_f(gv[3]);
    c = fg * c + ig * gg;
    return og * tanh_f(c);
}

// Broadcast lane values 0..5 of each 8-lane group into packed h[3].
__device__ __forceinline__ void bcast8(float v, unsigned long long h[3]) {
    const float e0 = __shfl_sync(0xffffffffu, v, 0, 8);
    const float e1 = __shfl_sync(0xffffffffu, v, 1, 8);
    const float e2 = __shfl_sync(0xffffffffu, v, 2, 8);
    const float e3 = __shfl_sync(0xffffffffu, v, 3, 8);
    const float e4 = __shfl_sync(0xffffffffu, v, 4, 8);
    const float e5 = __shfl_sync(0xffffffffu, v, 5, 8);
    h[0] = pack2(e0, e1);
    h[1] = pack2(e2, e3);
    h[2] = pack2(e4, e5);
}

__global__ __launch_bounds__(32) void lstm2_kernel(
    const float* __restrict__ x,
    const float* __restrict__ wih0, const float* __restrict__ whh0,
    const float* __restrict__ bi0,  const float* __restrict__ bh0,
    const float* __restrict__ wih1, const float* __restrict__ whh1,
    const float* __restrict__ bi1,  const float* __restrict__ bh1,
    float* __restrict__ out)
{
    const int tid = blockIdx.x * 32 + threadIdx.x;
    const int b   = tid >> 3;          // batch element (group of 8 lanes)
    const int j   = tid & 7;           // hidden index role
    const bool active = (j < 6);

    // ---- Register-resident weights (packed f32x2). Inactive lanes zeroed.
    unsigned long long Wi0[4][3], Wh0[4][3], Wi1[4][3], Wh1[4][3];
    float B0[4], B1[4];
    const int jj = active ? j : 0;
    const float m = active ? 1.0f : 0.0f;
#pragma unroll
    for (int g = 0; g < 4; g++) {
        const int r = g * 6 + jj;      // gate row within i,f,g,o blocks
#pragma unroll
        for (int p = 0; p < 3; p++) {
            Wi0[g][p] = pack2(m * wih0[r * 6 + 2 * p], m * wih0[r * 6 + 2 * p + 1]);
            Wh0[g][p] = pack2(m * whh0[r * 6 + 2 * p], m * whh0[r * 6 + 2 * p + 1]);
            Wi1[g][p] = pack2(m * wih1[r * 6 + 2 * p], m * wih1[r * 6 + 2 * p + 1]);
            Wh1[g][p] = pack2(m * whh1[r * 6 + 2 * p], m * whh1[r * 6 + 2 * p + 1]);
        }
        B0[g] = m * (bi0[r] + bh0[r]);
        B1[g] = m * (bi1[r] + bh1[r]);
    }

    // ---- Recurrent state
    unsigned long long hA[3] = {0ull, 0ull, 0ull};   // layer-0 hidden (t-1)
    unsigned long long hB[3] = {0ull, 0ull, 0ull};   // layer-1 hidden
    float c0 = 0.0f, c1 = 0.0f;

    const float2* xp = reinterpret_cast<const float2*>(x) + (size_t)b * (T_STEPS * 3);
    float* op = out + (size_t)b * (T_STEPS * 6) + j;

    // ---- Prologue: layer-0 step 0
    {
        const float2 a0 = xp[0], a1 = xp[1], a2 = xp[2];
        xp += 3;
        unsigned long long xv[3] = { pack2(a0.x, a0.y), pack2(a1.x, a1.y), pack2(a2.x, a2.y) };
        const float h0 = cell_step(Wi0, Wh0, B0, xv, hA, c0);
        bcast8(h0, hA);
    }

    // ---- Main loop: body t computes L0(t) and L1(t-1) — independent chains.
#pragma unroll 2
    for (int t = 1; t < T_STEPS; t++) {
        const float2 a0 = xp[0], a1 = xp[1], a2 = xp[2];
        xp += 3;
        unsigned long long xv[3] = { pack2(a0.x, a0.y), pack2(a1.x, a1.y), pack2(a2.x, a2.y) };

        // Chain A: layer 0, step t (reads hA = h0(t-1))
        const float h0 = cell_step(Wi0, Wh0, B0, xv, hA, c0);
        // Chain B: layer 1, step t-1 (reads hA = h0(t-1), hB = h1(t-2))
        const float h1 = cell_step(Wi1, Wh1, B1, hA, hB, c1);

        bcast8(h0, hA);
        bcast8(h1, hB);

        if (active) op[(size_t)(t - 1) * 6] = h1;
    }

    // ---- Epilogue: layer-1 step T-1
    {
        const float h1 = cell_step(Wi1, Wh1, B1, hA, hB, c1);
        if (active) op[(size_t)(T_STEPS - 1) * 6] = h1;
    }
}

extern "C" void kernel_launch(void* const* d_in, const int* in_sizes, int n_in,
                              void* d_out, int out_size) {
    const float* x    = (const float*)d_in[0];
    const float* wih0 = (const float*)d_in[1];
    const float* whh0 = (const float*)d_in[2];
    const float* bi0  = (const float*)d_in[3];
    const float* bh0  = (const float*)d_in[4];
    const float* wih1 = (const float*)d_in[5];
    const float* whh1 = (const float*)d_in[6];
    const float* bi1  = (const float*)d_in[7];
    const float* bh1  = (const float*)d_in[8];
    float* out = (float*)d_out;

    // 4096 batch * 8 lanes = 32768 threads; 32/block -> 1024 blocks
    // (small blocks: 6-7 warps/SM balance vs 2:1 imbalance at 128-thread blocks)
    lstm2_kernel<<<1024, 32>>>(x, wih0, whh0, bi0, bh0,
                               wih1, whh1, bi1, bh1, out);
}